// round 14
// baseline (speedup 1.0000x reference)
#include <cuda_runtime.h>
#include <cuda_bf16.h>

#define BATCH    4
#define NBOX     8192
#define TILE     128
#define THREADS  256
#define T_TILES  (NBOX / TILE)                  // 64
#define NPAIRS   (T_TILES * (T_TILES + 1) / 2)  // 2080

#define CINV (-0.34657359027997264f)   // 1/C = -ln2/2 ; C = -2/ln2

// Scratch (no device allocs).
__device__ float  g_part2[T_TILES][BATCH * NBOX];   // 8 MB
__device__ float  g_stage[8][BATCH * NBOX];         // 1 MB
__device__ float  g_adj[BATCH * NBOX];              // 128 KB
__device__ float4 g_sbox[BATCH * NBOX];             // sorted boxes (512 KB)
__device__ float  g_sscore[BATCH * NBOX];           // sorted scores (128 KB)
__device__ float2 g_tmeta[BATCH][T_TILES];          // (min_x1, max_x2) per tile
__device__ float  g_S[BATCH];                       // per-batch score sum
__device__ float  g_pmax[32];
__device__ float  g_p5[32][5];

// ---------------------------------------------------------------------------
// Kernel 0: per-batch sort by x1 (quantized-key bitonic in smem), gather
// boxes/scores into sorted order, emit per-tile (min_x1, max_x2) and S_b.
// Sort order only affects culling efficiency; correctness uses exact meta.
// ---------------------------------------------------------------------------
__global__ __launch_bounds__(1024)
void sort_kernel(const float* __restrict__ boxes,
                 const float* __restrict__ scores)
{
    const int b   = blockIdx.x;
    const int tid = threadIdx.x;

    __shared__ unsigned int skey[NBOX];   // 32 KB
    __shared__ int smaxi[T_TILES];
    __shared__ int smini[T_TILES];
    __shared__ float ssum[32];

    const float4* __restrict__ box4 = reinterpret_cast<const float4*>(boxes) + (size_t)b * NBOX;
    const float*  __restrict__ sc   = scores + (size_t)b * NBOX;

    for (int i = tid; i < NBOX; i += 1024) {
        float x1 = box4[i].x;                       // x1 in [0, 200)
        unsigned int k = (unsigned int)(x1 * 2621.44f);   // 19-bit quantized key
        if (k > 524287u) k = 524287u;
        skey[i] = (k << 13) | (unsigned int)i;
    }
    if (tid < T_TILES) { smaxi[tid] = 0; smini[tid] = 0x7fffffff; }
    __syncthreads();

    // bitonic sort (ascending), 8192 keys
    for (int k = 2; k <= NBOX; k <<= 1) {
        for (int j = k >> 1; j > 0; j >>= 1) {
            for (int i = tid; i < NBOX; i += 1024) {
                int ixj = i ^ j;
                if (ixj > i) {
                    unsigned int a = skey[i], c = skey[ixj];
                    bool up = ((i & k) == 0);
                    if (up ? (a > c) : (a < c)) { skey[i] = c; skey[ixj] = a; }
                }
            }
            __syncthreads();
        }
    }

    // gather + per-tile meta + score sum
    float mysum = 0.0f;
    for (int i = tid; i < NBOX; i += 1024) {
        int src = (int)(skey[i] & 8191u);
        float4 v = box4[src];
        float  s = sc[src];
        g_sbox[(size_t)b * NBOX + i]   = v;
        g_sscore[(size_t)b * NBOX + i] = s;
        mysum += s;                                  // fixed per-thread order
        int t = i >> 7;                              // tile index
        atomicMax(&smaxi[t], __float_as_int(v.z));   // x2 > 0: int-monotonic
        atomicMin(&smini[t], __float_as_int(v.x));   // x1 >= 0
    }
    __syncthreads();
    if (tid < T_TILES)
        g_tmeta[b][tid] = make_float2(__int_as_float(smini[tid]),
                                      __int_as_float(smaxi[tid]));

    // deterministic S_b: warp butterfly + fixed-order cross-warp
    #pragma unroll
    for (int o = 16; o; o >>= 1) mysum += __shfl_xor_sync(0xffffffffu, mysum, o);
    if ((tid & 31) == 0) ssum[tid >> 5] = mysum;
    __syncthreads();
    if (tid == 0) {
        float S = ssum[0];
        #pragma unroll
        for (int w = 1; w < 32; ++w) S = __fadd_rn(S, ssum[w]);
        g_S[b] = S;
    }
}

// ---------------------------------------------------------------------------
// Kernel 1: symmetric tile-pair kernel on SORTED data, accumulating (w-1)*s.
// Pair (ti <= tj); culled entirely (zero writes) if min_x1(tj) >= max_x2(ti)
// (exact: implies iw<=0 for every cross pair). 8x8 sub-block per thread,
// conflict-free rotated column order.
// ---------------------------------------------------------------------------
template<bool DIAG>
__device__ __forceinline__ void tile_body(
    const float4* __restrict__ sboxI, const float2* __restrict__ sasI,
    const float4* __restrict__ sboxJ, const float2* __restrict__ sasJ,
    int rg, int cg, float* __restrict__ racc, float* __restrict__ cacc)
{
    float4 rb[8]; float raInv[8]; float rs[8];
    #pragma unroll
    for (int r = 0; r < 8; ++r) {
        int ir = rg * 8 + r;
        rb[r] = sboxI[ir];
        float2 t = sasI[ir];
        raInv[r] = t.x * CINV;    // area_i / C
        rs[r]    = t.y;
    }

    #pragma unroll
    for (int c = 0; c < 8; ++c) {
        const int jc = cg * 8 + ((c + cg) & 7);   // rotated -> conflict-free LDS
        const float4 jb = sboxJ[jc];
        const float2 ja = sasJ[jc];
        const float jaInv = ja.x * CINV;          // area_j / C
        float ca = 0.0f;
        #pragma unroll
        for (int r = 0; r < 8; ++r) {
            float iw = fmaxf(fminf(rb[r].z, jb.z) - fmaxf(rb[r].x, jb.x), 0.0f);
            float ih = fmaxf(fminf(rb[r].w, jb.w) - fmaxf(rb[r].y, jb.y), 0.0f);
            float inter = iw * ih;
            float uniS = fmaf(inter, -CINV, raInv[r] + jaInv);  // union / C (<0)
            float rc; asm("rcp.approx.ftz.f32 %0, %1;" : "=f"(rc) : "f"(uniS));
            float t = inter * rc;                               // C * iou
            float w; asm("ex2.approx.ftz.f32 %0, %1;" : "=f"(w) : "f"(t));
            float w1 = w - 1.0f;                                // ==0 when inter==0
            if (DIAG) w1 = (jc > rg * 8 + r) ? w1 : 0.0f;       // strict upper only
            racc[r] = fmaf(w1, ja.y, racc[r]);
            ca      = fmaf(w1, rs[r], ca);
        }
        cacc[c] = __fadd_rn(cacc[c], ca);
    }
}

__global__ __launch_bounds__(THREADS, 2)
void symm_kernel()
{
    const int b = blockIdx.y;

    // triangular decode: pair index -> (ti, tj), ti <= tj
    const int p = blockIdx.x;
    int ti = (int)((2.0f * T_TILES + 1.0f
                    - sqrtf((2.0f * T_TILES + 1.0f) * (2.0f * T_TILES + 1.0f) - 8.0f * p)) * 0.5f);
    ti = ti < 0 ? 0 : (ti >= T_TILES ? T_TILES - 1 : ti);
    #pragma unroll 1
    while (ti > 0 && (ti * (2 * T_TILES - ti + 1)) / 2 > p) --ti;
    #pragma unroll 1
    while (((ti + 1) * (2 * T_TILES - ti)) / 2 <= p) ++ti;
    const int tj = ti + (p - (ti * (2 * T_TILES - ti + 1)) / 2);
    const bool diag = (ti == tj);

    const int tid   = threadIdx.x;
    const int ibase = ti * TILE;
    const int jbase = tj * TILE;

    float* __restrict__ prow = &g_part2[tj][(size_t)b * NBOX];
    float* __restrict__ pcol = &g_part2[ti][(size_t)b * NBOX];

    // ---- exact cull: no cross pair can overlap in x ----
    {
        float2 mi = g_tmeta[b][ti];
        float2 mj = g_tmeta[b][tj];
        if (mj.x >= mi.y) {          // min_x1(tj) >= max_x2(ti)
            if (tid < TILE) {
                prow[ibase + tid] = 0.0f;
                pcol[jbase + tid] = 0.0f;
            }
            return;
        }
    }

    __shared__ float4 sboxI[TILE];
    __shared__ float2 sasI[TILE];
    __shared__ float4 sboxJ[TILE];
    __shared__ float2 sasJ[TILE];
    __shared__ float  red[TILE * 17];

    const int rg = tid >> 4;      // 0..15
    const int cg = tid & 15;      // 0..15

    // stage both tiles from SORTED arrays
    if (tid < TILE) {
        float4 v = g_sbox[(size_t)b * NBOX + ibase + tid];
        sboxI[tid] = v;
        sasI[tid]  = make_float2((v.z - v.x) * (v.w - v.y),
                                 g_sscore[(size_t)b * NBOX + ibase + tid]);
    } else {
        int k = tid - TILE;
        float4 v = g_sbox[(size_t)b * NBOX + jbase + k];
        sboxJ[k] = v;
        sasJ[k]  = make_float2((v.z - v.x) * (v.w - v.y),
                               g_sscore[(size_t)b * NBOX + jbase + k]);
    }
    __syncthreads();

    float racc[8] = {0,0,0,0,0,0,0,0};
    float cacc[8] = {0,0,0,0,0,0,0,0};

    if (diag) tile_body<true >(sboxI, sasI, sboxJ, sasJ, rg, cg, racc, cacc);
    else      tile_body<false>(sboxI, sasI, sboxJ, sasJ, rg, cg, racc, cacc);

    // ---- row reduce: 16 col-groups, fixed order ----
    #pragma unroll
    for (int r = 0; r < 8; ++r)
        red[(rg * 8 + r) * 17 + cg] = racc[r];
    __syncthreads();

    float rowsum = 0.0f;
    if (tid < TILE) {
        rowsum = red[tid * 17 + 0];
        #pragma unroll
        for (int k = 1; k < 16; ++k)
            rowsum = __fadd_rn(rowsum, red[tid * 17 + k]);
    }
    __syncthreads();

    // ---- col reduce: 16 row-groups, store at rotated col jc ----
    #pragma unroll
    for (int c = 0; c < 8; ++c) {
        const int jc = cg * 8 + ((c + cg) & 7);
        red[jc * 17 + rg] = cacc[c];
    }
    __syncthreads();

    float colsum = 0.0f;
    if (tid < TILE) {
        colsum = red[tid * 17 + 0];
        #pragma unroll
        for (int k = 1; k < 16; ++k)
            colsum = __fadd_rn(colsum, red[tid * 17 + k]);
    }

    // ---- store partials ----
    if (tid < TILE) {
        if (diag) {
            const float E2M1 = -0.86466471676338730f;   // exp(-2) - 1 self term
            float v = __fadd_rn(__fadd_rn(rowsum, colsum), E2M1 * sasI[tid].y);
            prow[ibase + tid] = v;                       // prow == pcol here
        } else {
            prow[ibase + tid] = rowsum;
            pcol[jbase + tid] = colsum;
        }
    }
}

// ---------------------------------------------------------------------------
// Kernel 2a: stage A reduce — 64 slots -> 8 groups. 256 CTAs x 256 threads.
// ---------------------------------------------------------------------------
__global__ __launch_bounds__(256)
void reduceA_kernel()
{
    const int g     = blockIdx.x & 7;
    const int chunk = blockIdx.x >> 3;
    const int idx   = chunk * 256 + threadIdx.x;

    float4 a = reinterpret_cast<const float4*>(g_part2[g * 8 + 0])[idx];
    #pragma unroll
    for (int s = 1; s < 8; ++s) {
        float4 v = reinterpret_cast<const float4*>(g_part2[g * 8 + s])[idx];
        a.x = __fadd_rn(a.x, v.x); a.y = __fadd_rn(a.y, v.y);
        a.z = __fadd_rn(a.z, v.z); a.w = __fadd_rn(a.w, v.w);
    }
    reinterpret_cast<float4*>(g_stage[g])[idx] = a;
}

// ---------------------------------------------------------------------------
// Kernel 2b: stage B reduce — 8 groups -> g_adj (+ S_b), + per-CTA max.
// 32 CTAs x 256 threads.
// ---------------------------------------------------------------------------
__global__ __launch_bounds__(256)
void reduceB_kernel()
{
    const int idx = blockIdx.x * 256 + threadIdx.x;
    const int b   = blockIdx.x >> 3;
    const float S = g_S[b];

    float4 a = reinterpret_cast<const float4*>(g_stage[0])[idx];
    #pragma unroll
    for (int s = 1; s < 8; ++s) {
        float4 v = reinterpret_cast<const float4*>(g_stage[s])[idx];
        a.x = __fadd_rn(a.x, v.x); a.y = __fadd_rn(a.y, v.y);
        a.z = __fadd_rn(a.z, v.z); a.w = __fadd_rn(a.w, v.w);
    }
    a.x = __fadd_rn(a.x, S); a.y = __fadd_rn(a.y, S);
    a.z = __fadd_rn(a.z, S); a.w = __fadd_rn(a.w, S);
    reinterpret_cast<float4*>(g_adj)[idx] = a;

    __shared__ float smax[8];
    float m = fmaxf(fmaxf(a.x, a.y), fmaxf(a.z, a.w));
    #pragma unroll
    for (int o = 16; o; o >>= 1) m = fmaxf(m, __shfl_xor_sync(0xffffffffu, m, o));
    if ((threadIdx.x & 31) == 0) smax[threadIdx.x >> 5] = m;
    __syncthreads();
    if (threadIdx.x == 0) {
        float mm = smax[0];
        #pragma unroll
        for (int w = 1; w < 8; ++w) mm = fmaxf(mm, smax[w]);
        g_pmax[blockIdx.x] = mm;
    }
}

// ---------------------------------------------------------------------------
// Kernel 3: partial softmax sums over SORTED boxes (permutation-invariant).
// 32 CTAs (8 per batch) x 256 threads.
// ---------------------------------------------------------------------------
__global__ __launch_bounds__(256)
void softpart_kernel()
{
    const int cta = blockIdx.x;
    const int b   = cta >> 3;
    const int t   = threadIdx.x;

    float m = g_pmax[b * 8 + 0];
    #pragma unroll
    for (int k = 1; k < 8; ++k) m = fmaxf(m, g_pmax[b * 8 + k]);

    const int idx = cta * 256 + t;
    const float4 ad = reinterpret_cast<const float4*>(g_adj)[idx];

    float e0 = __expf(ad.x - m);
    float e1 = __expf(ad.y - m);
    float e2 = __expf(ad.z - m);
    float e3 = __expf(ad.w - m);

    float4 b0 = g_sbox[idx * 4 + 0];
    float4 b1 = g_sbox[idx * 4 + 1];
    float4 b2 = g_sbox[idx * 4 + 2];
    float4 b3 = g_sbox[idx * 4 + 3];

    float se  = ((e0 + e1) + (e2 + e3));
    float sx1 = fmaf(e0, b0.x, fmaf(e1, b1.x, fmaf(e2, b2.x, e3 * b3.x)));
    float sy1 = fmaf(e0, b0.y, fmaf(e1, b1.y, fmaf(e2, b2.y, e3 * b3.y)));
    float sx2 = fmaf(e0, b0.z, fmaf(e1, b1.z, fmaf(e2, b2.z, e3 * b3.z)));
    float sy2 = fmaf(e0, b0.w, fmaf(e1, b1.w, fmaf(e2, b2.w, e3 * b3.w)));

    __shared__ float s5[5][8];
    #pragma unroll
    for (int o = 16; o; o >>= 1) {
        se  += __shfl_xor_sync(0xffffffffu, se,  o);
        sx1 += __shfl_xor_sync(0xffffffffu, sx1, o);
        sy1 += __shfl_xor_sync(0xffffffffu, sy1, o);
        sx2 += __shfl_xor_sync(0xffffffffu, sx2, o);
        sy2 += __shfl_xor_sync(0xffffffffu, sy2, o);
    }
    if ((t & 31) == 0) {
        int w = t >> 5;
        s5[0][w] = se; s5[1][w] = sx1; s5[2][w] = sy1; s5[3][w] = sx2; s5[4][w] = sy2;
    }
    __syncthreads();
    if (t < 5) {
        float a = s5[t][0];
        #pragma unroll
        for (int w = 1; w < 8; ++w) a = __fadd_rn(a, s5[t][w]);
        g_p5[cta][t] = a;
    }
}

// ---------------------------------------------------------------------------
// Kernel 4: final combine. 4 CTAs x 32 threads.
// ---------------------------------------------------------------------------
__global__ __launch_bounds__(32)
void final_kernel(float* __restrict__ out)
{
    const int b = blockIdx.x;
    if (threadIdx.x == 0) {
        float a[5] = {0.f, 0.f, 0.f, 0.f, 0.f};
        #pragma unroll
        for (int k = 0; k < 8; ++k)
            #pragma unroll
            for (int q = 0; q < 5; ++q)
                a[q] = __fadd_rn(a[q], g_p5[b * 8 + k][q]);
        float inv = 1.0f / a[0];
        out[b * 4 + 0] = a[1] * inv;
        out[b * 4 + 1] = a[2] * inv;
        out[b * 4 + 2] = a[3] * inv;
        out[b * 4 + 3] = a[4] * inv;
    }
}

// ---------------------------------------------------------------------------
extern "C" void kernel_launch(void* const* d_in, const int* in_sizes, int n_in,
                              void* d_out, int out_size)
{
    const float* boxes  = (const float*)d_in[0];
    const float* scores = (const float*)d_in[1];
    if (n_in >= 2 && in_sizes[0] == BATCH * NBOX && in_sizes[1] == BATCH * NBOX * 4) {
        const float* tmp = boxes; boxes = scores; scores = tmp;
    }
    float* out = (float*)d_out;

    sort_kernel<<<BATCH, 1024>>>(boxes, scores);
    symm_kernel<<<dim3(NPAIRS, BATCH), THREADS>>>();
    reduceA_kernel<<<256, 256>>>();
    reduceB_kernel<<<32, 256>>>();
    softpart_kernel<<<32, 256>>>();
    final_kernel<<<BATCH, 32>>>(out);
}

// round 16
// speedup vs baseline: 1.6317x; 1.6317x over previous
#include <cuda_runtime.h>
#include <cuda_bf16.h>

#define BATCH    4
#define NBOX     8192
#define TILE     128
#define THREADS  256
#define T_TILES  (NBOX / TILE)                  // 64
#define NPAIRS   (T_TILES * (T_TILES + 1) / 2)  // 2080
#define NBINS    128

#define CINV (-0.34657359027997264f)   // 1/C = -ln2/2 ; C = -2/ln2

// Scratch (no device allocs).
__device__ float  g_part2[T_TILES][BATCH * NBOX];   // 8 MB
__device__ float  g_stage[8][BATCH * NBOX];         // 1 MB
__device__ float  g_adj[BATCH * NBOX];              // 128 KB
__device__ float4 g_sbox[BATCH * NBOX];             // bucketed boxes
__device__ float  g_sscore[BATCH * NBOX];           // bucketed scores
__device__ float2 g_tmeta[BATCH][T_TILES];          // exact (min_x1, max_x2) per tile
__device__ float  g_S[BATCH];                       // per-batch score sum
__device__ float  g_pmax[32];

// ---------------------------------------------------------------------------
// Kernel 0: deterministic counting-sort partition by x1 into NBINS buckets.
// One CTA (1024 threads = 32 warps) per batch. Element order is the fixed
// (warp, k, lane) schedule everywhere, so the permutation is deterministic.
// Emits bucketed boxes/scores, exact per-tile (min_x1, max_x2), and S_b.
// ---------------------------------------------------------------------------
__global__ __launch_bounds__(1024)
void bucket_kernel(const float* __restrict__ boxes,
                   const float* __restrict__ scores)
{
    const int b   = blockIdx.x;
    const int tid = threadIdx.x;
    const int w   = tid >> 5;
    const int l   = tid & 31;

    __shared__ int   hist[NBINS][33];    // counts, then reused as running counts
    __shared__ int   woff[NBINS][33];    // scatter bases per (bin, warp)
    __shared__ int   binBase[NBINS];
    __shared__ int   smaxi[T_TILES];
    __shared__ int   smini[T_TILES];
    __shared__ float ssum[32];

    const float4* __restrict__ box4 = reinterpret_cast<const float4*>(boxes) + (size_t)b * NBOX;
    const float*  __restrict__ sc   = scores + (size_t)b * NBOX;

    for (int i = tid; i < NBINS * 33; i += 1024) (&hist[0][0])[i] = 0;
    if (tid < T_TILES) { smaxi[tid] = 0; smini[tid] = 0x7fffffff; }
    __syncthreads();

    // ---- phase 1: per-(bin,warp) histogram, fixed (k,lane) order ----
    int mybin[8];
    #pragma unroll
    for (int k = 0; k < 8; ++k) {
        int idx = w * 256 + k * 32 + l;
        float x1 = box4[idx].x;
        int bin = (int)(x1 * (NBINS / 200.0f));
        bin = bin < 0 ? 0 : (bin > NBINS - 1 ? NBINS - 1 : bin);
        mybin[k] = bin;
        unsigned mask = __match_any_sync(0xffffffffu, bin);
        if (l == __ffs(mask) - 1) hist[bin][w] += __popc(mask);
        __syncwarp();
    }
    __syncthreads();

    // ---- phase 2: lexicographic (bin, warp) exclusive scan ----
    if (tid < NBINS) {
        int s = 0;
        #pragma unroll 1
        for (int ww = 0; ww < 32; ++ww) s += hist[tid][ww];
        binBase[tid] = s;                 // temp: bin totals
    }
    __syncthreads();
    if (tid == 0) {
        int acc = 0;
        #pragma unroll 1
        for (int bin = 0; bin < NBINS; ++bin) {
            int t = binBase[bin]; binBase[bin] = acc; acc += t;
        }
    }
    __syncthreads();
    if (tid < NBINS) {
        int acc = binBase[tid];
        #pragma unroll 1
        for (int ww = 0; ww < 32; ++ww) { woff[tid][ww] = acc; acc += hist[tid][ww]; }
    }
    __syncthreads();
    // re-zero hist -> running counts for scatter
    for (int i = tid; i < NBINS * 33; i += 1024) (&hist[0][0])[i] = 0;
    __syncthreads();

    // ---- phase 3: deterministic scatter + exact tile meta + S_b ----
    float4* __restrict__ dstB = g_sbox   + (size_t)b * NBOX;
    float*  __restrict__ dstS = g_sscore + (size_t)b * NBOX;

    float mysum = 0.0f;
    #pragma unroll
    for (int k = 0; k < 8; ++k) {
        int idx = w * 256 + k * 32 + l;
        int bin = mybin[k];
        unsigned mask  = __match_any_sync(0xffffffffu, bin);
        int      myoff = __popc(mask & ((1u << l) - 1u));
        int      base  = hist[bin][w];      // all matched lanes read same value
        __syncwarp();
        if (l == __ffs(mask) - 1) hist[bin][w] = base + __popc(mask);
        __syncwarp();
        int pos = woff[bin][w] + base + myoff;

        float4 v = box4[idx];
        float  s = sc[idx];
        dstB[pos] = v;
        dstS[pos] = s;
        mysum += s;                          // fixed per-thread order

        int t = pos >> 7;                    // tile of scattered position
        atomicMax(&smaxi[t], __float_as_int(v.z));   // x2 > 0: int-monotonic
        atomicMin(&smini[t], __float_as_int(v.x));   // x1 >= 0
    }
    __syncthreads();
    if (tid < T_TILES)
        g_tmeta[b][tid] = make_float2(__int_as_float(smini[tid]),
                                      __int_as_float(smaxi[tid]));

    // deterministic S_b
    #pragma unroll
    for (int o = 16; o; o >>= 1) mysum += __shfl_xor_sync(0xffffffffu, mysum, o);
    if (l == 0) ssum[w] = mysum;
    __syncthreads();
    if (tid == 0) {
        float S = ssum[0];
        #pragma unroll
        for (int ww = 1; ww < 32; ++ww) S = __fadd_rn(S, ssum[ww]);
        g_S[b] = S;
    }
}

// ---------------------------------------------------------------------------
// Kernel 1: symmetric tile-pair kernel on BUCKETED data, accumulating (w-1)*s.
// Pair (ti <= tj) culled entirely if min_x1(tj) >= max_x2(ti) (exact).
// 8x8 sub-block per thread, conflict-free rotated column order.
// ---------------------------------------------------------------------------
template<bool DIAG>
__device__ __forceinline__ void tile_body(
    const float4* __restrict__ sboxI, const float2* __restrict__ sasI,
    const float4* __restrict__ sboxJ, const float2* __restrict__ sasJ,
    int rg, int cg, float* __restrict__ racc, float* __restrict__ cacc)
{
    float4 rb[8]; float raInv[8]; float rs[8];
    #pragma unroll
    for (int r = 0; r < 8; ++r) {
        int ir = rg * 8 + r;
        rb[r] = sboxI[ir];
        float2 t = sasI[ir];
        raInv[r] = t.x * CINV;
        rs[r]    = t.y;
    }

    #pragma unroll
    for (int c = 0; c < 8; ++c) {
        const int jc = cg * 8 + ((c + cg) & 7);   // rotated -> conflict-free LDS
        const float4 jb = sboxJ[jc];
        const float2 ja = sasJ[jc];
        const float jaInv = ja.x * CINV;
        float ca = 0.0f;
        #pragma unroll
        for (int r = 0; r < 8; ++r) {
            float iw = fmaxf(fminf(rb[r].z, jb.z) - fmaxf(rb[r].x, jb.x), 0.0f);
            float ih = fmaxf(fminf(rb[r].w, jb.w) - fmaxf(rb[r].y, jb.y), 0.0f);
            float inter = iw * ih;
            float uniS = fmaf(inter, -CINV, raInv[r] + jaInv);  // union / C (<0)
            float rc; asm("rcp.approx.ftz.f32 %0, %1;" : "=f"(rc) : "f"(uniS));
            float t = inter * rc;                               // C * iou
            float w; asm("ex2.approx.ftz.f32 %0, %1;" : "=f"(w) : "f"(t));
            float w1 = w - 1.0f;                                // ==0 when inter==0
            if (DIAG) w1 = (jc > rg * 8 + r) ? w1 : 0.0f;       // strict upper only
            racc[r] = fmaf(w1, ja.y, racc[r]);
            ca      = fmaf(w1, rs[r], ca);
        }
        cacc[c] = __fadd_rn(cacc[c], ca);
    }
}

__global__ __launch_bounds__(THREADS, 2)
void symm_kernel()
{
    const int b = blockIdx.y;

    const int p = blockIdx.x;
    int ti = (int)((2.0f * T_TILES + 1.0f
                    - sqrtf((2.0f * T_TILES + 1.0f) * (2.0f * T_TILES + 1.0f) - 8.0f * p)) * 0.5f);
    ti = ti < 0 ? 0 : (ti >= T_TILES ? T_TILES - 1 : ti);
    #pragma unroll 1
    while (ti > 0 && (ti * (2 * T_TILES - ti + 1)) / 2 > p) --ti;
    #pragma unroll 1
    while (((ti + 1) * (2 * T_TILES - ti)) / 2 <= p) ++ti;
    const int tj = ti + (p - (ti * (2 * T_TILES - ti + 1)) / 2);
    const bool diag = (ti == tj);

    const int tid   = threadIdx.x;
    const int ibase = ti * TILE;
    const int jbase = tj * TILE;

    float* __restrict__ prow = &g_part2[tj][(size_t)b * NBOX];
    float* __restrict__ pcol = &g_part2[ti][(size_t)b * NBOX];

    // ---- exact cull: no cross pair can overlap in x ----
    {
        float2 mi = g_tmeta[b][ti];
        float2 mj = g_tmeta[b][tj];
        if (mj.x >= mi.y) {
            if (tid < TILE) {
                prow[ibase + tid] = 0.0f;
                pcol[jbase + tid] = 0.0f;
            }
            return;
        }
    }

    __shared__ float4 sboxI[TILE];
    __shared__ float2 sasI[TILE];
    __shared__ float4 sboxJ[TILE];
    __shared__ float2 sasJ[TILE];
    __shared__ float  red[TILE * 17];

    const int rg = tid >> 4;
    const int cg = tid & 15;

    if (tid < TILE) {
        float4 v = g_sbox[(size_t)b * NBOX + ibase + tid];
        sboxI[tid] = v;
        sasI[tid]  = make_float2((v.z - v.x) * (v.w - v.y),
                                 g_sscore[(size_t)b * NBOX + ibase + tid]);
    } else {
        int k = tid - TILE;
        float4 v = g_sbox[(size_t)b * NBOX + jbase + k];
        sboxJ[k] = v;
        sasJ[k]  = make_float2((v.z - v.x) * (v.w - v.y),
                               g_sscore[(size_t)b * NBOX + jbase + k]);
    }
    __syncthreads();

    float racc[8] = {0,0,0,0,0,0,0,0};
    float cacc[8] = {0,0,0,0,0,0,0,0};

    if (diag) tile_body<true >(sboxI, sasI, sboxJ, sasJ, rg, cg, racc, cacc);
    else      tile_body<false>(sboxI, sasI, sboxJ, sasJ, rg, cg, racc, cacc);

    #pragma unroll
    for (int r = 0; r < 8; ++r)
        red[(rg * 8 + r) * 17 + cg] = racc[r];
    __syncthreads();

    float rowsum = 0.0f;
    if (tid < TILE) {
        rowsum = red[tid * 17 + 0];
        #pragma unroll
        for (int k = 1; k < 16; ++k)
            rowsum = __fadd_rn(rowsum, red[tid * 17 + k]);
    }
    __syncthreads();

    #pragma unroll
    for (int c = 0; c < 8; ++c) {
        const int jc = cg * 8 + ((c + cg) & 7);
        red[jc * 17 + rg] = cacc[c];
    }
    __syncthreads();

    float colsum = 0.0f;
    if (tid < TILE) {
        colsum = red[tid * 17 + 0];
        #pragma unroll
        for (int k = 1; k < 16; ++k)
            colsum = __fadd_rn(colsum, red[tid * 17 + k]);
    }

    if (tid < TILE) {
        if (diag) {
            const float E2M1 = -0.86466471676338730f;   // exp(-2) - 1 self term
            float v = __fadd_rn(__fadd_rn(rowsum, colsum), E2M1 * sasI[tid].y);
            prow[ibase + tid] = v;
        } else {
            prow[ibase + tid] = rowsum;
            pcol[jbase + tid] = colsum;
        }
    }
}

// ---------------------------------------------------------------------------
// Kernel 2a: stage A reduce — 64 slots -> 8 groups. 256 CTAs x 256 threads.
// ---------------------------------------------------------------------------
__global__ __launch_bounds__(256)
void reduceA_kernel()
{
    const int g     = blockIdx.x & 7;
    const int chunk = blockIdx.x >> 3;
    const int idx   = chunk * 256 + threadIdx.x;

    float4 a = reinterpret_cast<const float4*>(g_part2[g * 8 + 0])[idx];
    #pragma unroll
    for (int s = 1; s < 8; ++s) {
        float4 v = reinterpret_cast<const float4*>(g_part2[g * 8 + s])[idx];
        a.x = __fadd_rn(a.x, v.x); a.y = __fadd_rn(a.y, v.y);
        a.z = __fadd_rn(a.z, v.z); a.w = __fadd_rn(a.w, v.w);
    }
    reinterpret_cast<float4*>(g_stage[g])[idx] = a;
}

// ---------------------------------------------------------------------------
// Kernel 2b: stage B reduce — 8 groups -> g_adj (+ S_b), + per-CTA max.
// ---------------------------------------------------------------------------
__global__ __launch_bounds__(256)
void reduceB_kernel()
{
    const int idx = blockIdx.x * 256 + threadIdx.x;
    const int b   = blockIdx.x >> 3;
    const float S = g_S[b];

    float4 a = reinterpret_cast<const float4*>(g_stage[0])[idx];
    #pragma unroll
    for (int s = 1; s < 8; ++s) {
        float4 v = reinterpret_cast<const float4*>(g_stage[s])[idx];
        a.x = __fadd_rn(a.x, v.x); a.y = __fadd_rn(a.y, v.y);
        a.z = __fadd_rn(a.z, v.z); a.w = __fadd_rn(a.w, v.w);
    }
    a.x = __fadd_rn(a.x, S); a.y = __fadd_rn(a.y, S);
    a.z = __fadd_rn(a.z, S); a.w = __fadd_rn(a.w, S);
    reinterpret_cast<float4*>(g_adj)[idx] = a;

    __shared__ float smax[8];
    float m = fmaxf(fmaxf(a.x, a.y), fmaxf(a.z, a.w));
    #pragma unroll
    for (int o = 16; o; o >>= 1) m = fmaxf(m, __shfl_xor_sync(0xffffffffu, m, o));
    if ((threadIdx.x & 31) == 0) smax[threadIdx.x >> 5] = m;
    __syncthreads();
    if (threadIdx.x == 0) {
        float mm = smax[0];
        #pragma unroll
        for (int w = 1; w < 8; ++w) mm = fmaxf(mm, smax[w]);
        g_pmax[blockIdx.x] = mm;
    }
}

// ---------------------------------------------------------------------------
// Kernel 3: per-batch softmax + weighted average (permutation-invariant over
// bucketed boxes). 4 CTAs x 1024 threads, 2 float4 per thread.
// ---------------------------------------------------------------------------
__global__ __launch_bounds__(1024)
void softfinal_kernel(float* __restrict__ out)
{
    const int b = blockIdx.x;
    const int t = threadIdx.x;

    float m = g_pmax[b * 8 + 0];
    #pragma unroll
    for (int k = 1; k < 8; ++k) m = fmaxf(m, g_pmax[b * 8 + k]);

    float se = 0.f, sx1 = 0.f, sy1 = 0.f, sx2 = 0.f, sy2 = 0.f;
    #pragma unroll
    for (int h = 0; h < 2; ++h) {
        int idx = b * 2048 + h * 1024 + t;   // f4 index
        float4 ad = reinterpret_cast<const float4*>(g_adj)[idx];
        float e0 = __expf(ad.x - m);
        float e1 = __expf(ad.y - m);
        float e2 = __expf(ad.z - m);
        float e3 = __expf(ad.w - m);
        float4 b0 = g_sbox[idx * 4 + 0];
        float4 b1 = g_sbox[idx * 4 + 1];
        float4 b2 = g_sbox[idx * 4 + 2];
        float4 b3 = g_sbox[idx * 4 + 3];
        se  += ((e0 + e1) + (e2 + e3));
        sx1 = fmaf(e0, b0.x, fmaf(e1, b1.x, fmaf(e2, b2.x, fmaf(e3, b3.x, sx1))));
        sy1 = fmaf(e0, b0.y, fmaf(e1, b1.y, fmaf(e2, b2.y, fmaf(e3, b3.y, sy1))));
        sx2 = fmaf(e0, b0.z, fmaf(e1, b1.z, fmaf(e2, b2.z, fmaf(e3, b3.z, sx2))));
        sy2 = fmaf(e0, b0.w, fmaf(e1, b1.w, fmaf(e2, b2.w, fmaf(e3, b3.w, sy2))));
    }

    __shared__ float s5[5][32];
    #pragma unroll
    for (int o = 16; o; o >>= 1) {
        se  += __shfl_xor_sync(0xffffffffu, se,  o);
        sx1 += __shfl_xor_sync(0xffffffffu, sx1, o);
        sy1 += __shfl_xor_sync(0xffffffffu, sy1, o);
        sx2 += __shfl_xor_sync(0xffffffffu, sx2, o);
        sy2 += __shfl_xor_sync(0xffffffffu, sy2, o);
    }
    if ((t & 31) == 0) {
        int w = t >> 5;
        s5[0][w] = se; s5[1][w] = sx1; s5[2][w] = sy1; s5[3][w] = sx2; s5[4][w] = sy2;
    }
    __syncthreads();
    if (t == 0) {
        float a[5];
        #pragma unroll
        for (int q = 0; q < 5; ++q) {
            float acc = s5[q][0];
            #pragma unroll
            for (int w = 1; w < 32; ++w) acc = __fadd_rn(acc, s5[q][w]);
            a[q] = acc;
        }
        float inv = 1.0f / a[0];
        out[b * 4 + 0] = a[1] * inv;
        out[b * 4 + 1] = a[2] * inv;
        out[b * 4 + 2] = a[3] * inv;
        out[b * 4 + 3] = a[4] * inv;
    }
}

// ---------------------------------------------------------------------------
extern "C" void kernel_launch(void* const* d_in, const int* in_sizes, int n_in,
                              void* d_out, int out_size)
{
    const float* boxes  = (const float*)d_in[0];
    const float* scores = (const float*)d_in[1];
    if (n_in >= 2 && in_sizes[0] == BATCH * NBOX && in_sizes[1] == BATCH * NBOX * 4) {
        const float* tmp = boxes; boxes = scores; scores = tmp;
    }
    float* out = (float*)d_out;

    bucket_kernel<<<BATCH, 1024>>>(boxes, scores);
    symm_kernel<<<dim3(NPAIRS, BATCH), THREADS>>>();
    reduceA_kernel<<<256, 256>>>();
    reduceB_kernel<<<32, 256>>>();
    softfinal_kernel<<<BATCH, 1024>>>(out);
}